// round 11
// baseline (speedup 1.0000x reference)
#include <cuda_runtime.h>
#include <cuda_fp16.h>
#include <cstdint>

#define NMAX 200000
#define D 128
#define BR 256
#define DEGI 296

// ---- smem layout (bytes) ----
#define HA_OFF    0        // hA: 256 x 272B
#define RS_OFF    69632    // rS: 256 x 144B
#define SLOTS_OFF 106496   // 2 pairs x (18432 + 18432); Wc uses pair0 (34816B)
#define BA_OFF    180224   // b1 (2048 f); also Win(384)+b_in(128) during x-staging
#define BB_OFF    188416   // attn bias (bc)
#define LNG_OFF   188928
#define LNB_OFF   189440
#define BB2_OFF   189952   // ffn final bias (b2)
#define LNG2_OFF  190464
#define LNB2_OFF  190976
#define RED_OFF   191488   // LN partials float2[256][2]; xS (768 f) during x-staging
#define ZRED_OFF  195584
#define WD_OFF    197632   // Wd 128 + bd
#define ITEM_OFF  198152
static const int SMEM_BYTES = 198160;
#define SL_PAIR 36864
#define SL_SZ   18432

__device__ float g_z[NMAX];
__device__ float g_deg[NMAX];
__device__ float g_dis[NMAX];
__device__ float g_u[NMAX];
__device__ float g_t[NMAX];
__device__ __half g_wh[1622016];  // [W1 3x262144 | W2 3x262144 | Wc 3x16384]
__device__ float g_bc[384];
__device__ int g_ctr;
#define OW1 0
#define OW2 786432
#define OWC 1572864

// ---------------------------------------------------------------------------
static __device__ __forceinline__ uint32_t smem_u32(const void* p) {
    uint32_t r;
    asm("{ .reg .u64 t; cvta.to.shared.u64 t, %1; cvt.u32.u64 %0, t; }" : "=r"(r) : "l"(p));
    return r;
}
static __device__ __forceinline__ void cp16h(uint32_t dst, const __half* src) {
    asm volatile("cp.async.cg.shared.global [%0], [%1], 16;\n" :: "r"(dst), "l"(src));
}
static __device__ __forceinline__ void cp_commit() { asm volatile("cp.async.commit_group;\n"); }
template <int NPEND>
static __device__ __forceinline__ void cp_wait() { asm volatile("cp.async.wait_group %0;\n" :: "n"(NPEND)); }

static __device__ __forceinline__ void ldsm4(uint32_t* r, uint32_t addr) {
    asm volatile("ldmatrix.sync.aligned.m8n8.x4.shared.b16 {%0,%1,%2,%3}, [%4];"
                 : "=r"(r[0]), "=r"(r[1]), "=r"(r[2]), "=r"(r[3]) : "r"(addr));
}
static __device__ __forceinline__ void mma16816(float* c, const uint32_t* a,
                                                uint32_t b0, uint32_t b1) {
    asm volatile("mma.sync.aligned.m16n8k16.row.col.f32.f16.f16.f32 "
                 "{%0,%1,%2,%3}, {%4,%5,%6,%7}, {%8,%9}, {%0,%1,%2,%3};"
                 : "+f"(c[0]), "+f"(c[1]), "+f"(c[2]), "+f"(c[3])
                 : "r"(a[0]), "r"(a[1]), "r"(a[2]), "r"(a[3]), "r"(b0), "r"(b1));
}

// ---------------------------------------------------------------------------
// One merged prep kernel: cvt W1, cvt W2, Wc=Wo@Wv, bc, deg_init, ctr reset.
__global__ void k_prep(const float* __restrict__ W1, const float* __restrict__ W2,
                       const float* __restrict__ Wo, const float* __restrict__ Wv,
                       const float* __restrict__ bv, const float* __restrict__ bo,
                       int N, int degblocks) {
    const int b = blockIdx.x, tid = threadIdx.x;
    if (b < 3072) {
        int i = b * 256 + tid;
        g_wh[OW1 + i] = __float2half_rn(W1[i]);
    } else if (b < 6144) {
        int i = (b - 3072) * 256 + tid;
        g_wh[OW2 + i] = __float2half_rn(W2[i]);
    } else if (b < 6528) {
        if (tid < 128) {
            int idx = b - 6144;
            int l = idx >> 7, o = idx & 127, d = tid;
            const float* wo = Wo + (size_t)(l * 128 + o) * 128;
            const float* wv = Wv + (size_t)l * 128 * 128;
            float s = 0.f;
#pragma unroll 8
            for (int k = 0; k < 128; k++) s += wo[k] * wv[k * 128 + d];
            g_wh[OWC + (size_t)(l * 128 + o) * 128 + d] = __float2half_rn(s);
        }
    } else if (b < 6576) {
        int wid = (b - 6528) * 8 + (tid >> 5);
        int lane = tid & 31;
        int l = wid >> 7;
        const float* wo = Wo + (size_t)wid * 128;
        float s = 0.f;
#pragma unroll
        for (int q = 0; q < 4; q++) s += wo[lane + q * 32] * bv[l * 128 + lane + q * 32];
#pragma unroll
        for (int o = 16; o; o >>= 1) s += __shfl_xor_sync(0xffffffffu, s, o);
        if (lane == 0) g_bc[wid] = s + bo[wid];
    } else if (b < 6576 + degblocks) {
        int n = (b - 6576) * 256 + tid;
        if (n < N) g_deg[n] = 1.0f;
    } else {
        if (tid == 0) g_ctr = 0;
    }
}

// ---------------------------------------------------------------------------
// Persistent mega-kernel: each item runs a 256-row tile through ALL 3 layers
// (row-local — no inter-tile deps), then trailing degree-count items.
__global__ __launch_bounds__(512, 1)
void mega(const float* __restrict__ x, const float* __restrict__ Win,
          const float* __restrict__ b_in,
          const float* __restrict__ b1, const float* __restrict__ b2,
          const float* __restrict__ ln1g, const float* __restrict__ ln1b,
          const float* __restrict__ ln2g, const float* __restrict__ ln2b,
          const float* __restrict__ Wd, const float* __restrict__ bd,
          const int* __restrict__ colE, int E, int N, int ntiles) {
    extern __shared__ __align__(256) unsigned char smem[];
    const int tid = threadIdx.x, w = tid >> 5, lane = tid & 31;
    const int wr = w >> 1, wc = w & 1, r0 = wr * 32;
    const uint32_t sb = smem_u32(smem);

    float* baS   = (float*)(smem + BA_OFF);
    float* bbS   = (float*)(smem + BB_OFF);
    float* lngS  = (float*)(smem + LNG_OFF);
    float* lnbS  = (float*)(smem + LNB_OFF);
    float* bb2S  = (float*)(smem + BB2_OFF);
    float* lng2S = (float*)(smem + LNG2_OFF);
    float* lnb2S = (float*)(smem + LNB2_OFF);
    float2* red  = (float2*)(smem + RED_OFF);
    float* zred  = (float*)(smem + ZRED_OFF);
    float* WdS   = (float*)(smem + WD_OFF);
    int* shitem  = (int*)(smem + ITEM_OFF);

    const uint32_t loff272 = (lane & 15) * 272 + (lane >> 4) * 16;
    const uint32_t loff144 = (lane & 15) * 144 + (lane >> 4) * 16;
    const uint32_t haA = sb + HA_OFF + r0 * 272 + loff272;

    for (;;) {
        if (tid == 0) *shitem = atomicAdd(&g_ctr, 1);
        __syncthreads();
        const int item = *shitem;
        if (item >= ntiles + DEGI) return;
        if (item >= ntiles) {
            int di = item - ntiles;
            int slice = (E + DEGI - 1) / DEGI;
            int e0 = di * slice;
            int e1 = e0 + slice; if (e1 > E) e1 = E;
            for (int e = e0 + tid; e < e1; e += 512)
                atomicAdd(&g_deg[colE[e]], 1.0f);
            continue;
        }
        const int row0 = item * BR;

        // ---- issue layer-0 weight copies ----
        {
            const __half* Wc0 = g_wh + OWC;
            for (int i = tid; i < 2048; i += 512) {
                int r = i >> 4, q = i & 15;
                cp16h(sb + SLOTS_OFF + r * 272 + q * 16, Wc0 + (size_t)r * 128 + q * 8);
            }
            cp_commit();
            const __half* Wa0 = g_wh + OW1;
            const __half* Wb0 = g_wh + OW2;
            for (int i = tid; i < 1024; i += 512) {
                int r = i >> 4, q = i & 15;
                cp16h(sb + SLOTS_OFF + SL_PAIR + r * 272 + q * 16, Wa0 + (size_t)r * 128 + q * 8);
            }
            for (int i = tid; i < 1024; i += 512) {
                int r = i >> 3, q = i & 7;
                cp16h(sb + SLOTS_OFF + SL_PAIR + SL_SZ + r * 144 + q * 16,
                      Wb0 + (size_t)r * 2048 + q * 8);
            }
            cp_commit();
        }

        // ---- x-projection staging: hA = relu(x @ Win^T + b_in) (fp16) ----
        {
            float* WinS = baS;
            float* binS = baS + 384;
            float* xS   = (float*)(smem + RED_OFF);
            if (tid < 384) WinS[tid] = Win[tid];
            else if (tid < 512) binS[tid - 384] = b_in[tid - 384];
            for (int i = tid; i < 768; i += 512) {
                int gi = row0 * 3 + i;
                xS[i] = (gi < N * 3) ? x[gi] : 0.f;
            }
            __syncthreads();
            for (int i = tid; i < BR * 64; i += 512) {
                int r = i >> 6, j = i & 63, c = 2 * j;
                int gr = row0 + r;
                float v0 = 0.f, v1 = 0.f;
                if (gr < N) {
                    float x0 = xS[r * 3], x1 = xS[r * 3 + 1], x2 = xS[r * 3 + 2];
                    v0 = fmaxf(binS[c] + x0 * WinS[c * 3] + x1 * WinS[c * 3 + 1]
                               + x2 * WinS[c * 3 + 2], 0.f);
                    v1 = fmaxf(binS[c + 1] + x0 * WinS[(c + 1) * 3] + x1 * WinS[(c + 1) * 3 + 1]
                               + x2 * WinS[(c + 1) * 3 + 2], 0.f);
                }
                __half2 h2 = __floats2half2_rn(v0, v1);
                *(uint32_t*)(smem + HA_OFF + r * 272 + j * 4) = *(uint32_t*)&h2;
            }
        }
        if (tid < 128) { WdS[tid] = Wd[tid]; }
        if (tid == 128) WdS[128] = bd[0];

        // ================= 3 transformer layers, tile-stationary =================
        for (int l = 0; l < 3; l++) {
            const __half* Wa = g_wh + OW1 + (size_t)l * 262144;
            const __half* Wb = g_wh + OW2 + (size_t)l * 262144;

            if (l > 0) {
                // pairs free (post-LN2 sync below); issue this layer's Wc + chunk0
                const __half* Wc = g_wh + OWC + (size_t)l * 16384;
                for (int i = tid; i < 2048; i += 512) {
                    int r = i >> 4, q = i & 15;
                    cp16h(sb + SLOTS_OFF + r * 272 + q * 16, Wc + (size_t)r * 128 + q * 8);
                }
                cp_commit();
                for (int i = tid; i < 1024; i += 512) {
                    int r = i >> 4, q = i & 15;
                    cp16h(sb + SLOTS_OFF + SL_PAIR + r * 272 + q * 16, Wa + (size_t)r * 128 + q * 8);
                }
                for (int i = tid; i < 1024; i += 512) {
                    int r = i >> 3, q = i & 7;
                    cp16h(sb + SLOTS_OFF + SL_PAIR + SL_SZ + r * 144 + q * 16,
                          Wb + (size_t)r * 2048 + q * 8);
                }
                cp_commit();
            }
            // per-layer biases
            if (tid < 128) {
                bbS[tid]   = g_bc[l * 128 + tid];
                lngS[tid]  = ln1g[l * 128 + tid];
                lnbS[tid]  = ln1b[l * 128 + tid];
                bb2S[tid]  = b2[l * 128 + tid];
                lng2S[tid] = ln2g[l * 128 + tid];
                lnb2S[tid] = ln2b[l * 128 + tid];
            }

            cp_wait<1>();     // Wc landed (chunk0 may fly)
            __syncthreads();  // hA + biases visible

            for (int i = tid; i < 2048; i += 512) baS[i] = b1[l * 2048 + i];

            float acc[2][8][4];
#pragma unroll
            for (int m = 0; m < 2; m++)
#pragma unroll
                for (int n = 0; n < 8; n++)
#pragma unroll
                    for (int e = 0; e < 4; e++) acc[m][n][e] = 0.f;

            // ======== attn GEMM: acc = hA @ Wc^T ========
            {
                const uint32_t bB = sb + SLOTS_OFF + (wc * 64) * 272 + loff272;
                uint32_t a[2][4], b[4][4];
#pragma unroll
                for (int kk = 0; kk < 8; kk++) {
                    ldsm4(a[0], haA + kk * 32);
                    ldsm4(a[1], haA + 16 * 272 + kk * 32);
#pragma unroll
                    for (int g = 0; g < 4; g++) ldsm4(b[g], bB + g * 16 * 272 + kk * 32);
#pragma unroll
                    for (int m = 0; m < 2; m++)
#pragma unroll
                        for (int n = 0; n < 8; n++)
                            mma16816(acc[m][n], a[m], b[n >> 1][n & 1], b[n >> 1][(n & 1) + 2]);
                }
            }
            __syncthreads();

            // ======== attn epilogue: LN1 -> hA (fp16) ========
#pragma unroll
            for (int m = 0; m < 2; m++)
#pragma unroll
                for (int h = 0; h < 2; h++) {
                    int lr = r0 + m * 16 + (lane >> 2) + h * 8;
                    int gr = row0 + lr;
                    float ss = 0.f, qq = 0.f;
                    if (gr < N) {
#pragma unroll
                        for (int n = 0; n < 8; n++) {
                            int c = wc * 64 + n * 8 + (lane & 3) * 2;
                            __half2 hh = *(__half2*)(smem + HA_OFF + lr * 272 + c * 2);
                            float2 ho = __half22float2(hh);
                            float v0 = acc[m][n][h * 2 + 0] + ho.x + bbS[c];
                            float v1 = acc[m][n][h * 2 + 1] + ho.y + bbS[c + 1];
                            ss += v0 + v1;
                            qq += v0 * v0 + v1 * v1;
                        }
                    }
                    ss += __shfl_xor_sync(0xffffffffu, ss, 1);
                    ss += __shfl_xor_sync(0xffffffffu, ss, 2);
                    qq += __shfl_xor_sync(0xffffffffu, qq, 1);
                    qq += __shfl_xor_sync(0xffffffffu, qq, 2);
                    if ((lane & 3) == 0) red[lr * 2 + wc] = make_float2(ss, qq);
                }
            asm volatile("bar.sync %0, 64;" :: "r"(1 + wr) : "memory");
#pragma unroll
            for (int m = 0; m < 2; m++)
#pragma unroll
                for (int h = 0; h < 2; h++) {
                    int lr = r0 + m * 16 + (lane >> 2) + h * 8;
                    int gr = row0 + lr;
                    if (gr >= N) continue;
                    float2 p0 = red[lr * 2 + 0], p1 = red[lr * 2 + 1];
                    float mean = (p0.x + p1.x) * (1.f / 128.f);
                    float inv = rsqrtf((p0.y + p1.y) * (1.f / 128.f) - mean * mean + 1e-5f);
#pragma unroll
                    for (int n = 0; n < 8; n++) {
                        int c = wc * 64 + n * 8 + (lane & 3) * 2;
                        __half2 hh = *(__half2*)(smem + HA_OFF + lr * 272 + c * 2);
                        float2 ho = __half22float2(hh);
                        float v0 = acc[m][n][h * 2 + 0] + ho.x + bbS[c];
                        float v1 = acc[m][n][h * 2 + 1] + ho.y + bbS[c + 1];
                        float o0 = (v0 - mean) * inv * lngS[c] + lnbS[c];
                        float o1 = (v1 - mean) * inv * lngS[c + 1] + lnbS[c + 1];
                        __half2 oo = __floats2half2_rn(o0, o1);
                        *(uint32_t*)(smem + HA_OFF + lr * 272 + c * 2) = *(uint32_t*)&oo;
                    }
                }
#pragma unroll
            for (int m = 0; m < 2; m++)
#pragma unroll
                for (int n = 0; n < 8; n++)
#pragma unroll
                    for (int e = 0; e < 4; e++) acc[m][n][e] = 0.f;

            // ======== FFN: 32 chunks; chunk c in pair ((c+1)&1) ========
            for (int ch = 0; ch < 32; ch++) {
                const int f0 = ch << 6;
                const uint32_t sWa = sb + SLOTS_OFF + (((ch + 1) & 1)) * SL_PAIR;
                const uint32_t sWb = sWa + SL_SZ;

                cp_wait<0>();
                __syncthreads();

                if (ch + 1 < 32) {
                    uint32_t nWa = sb + SLOTS_OFF + ((ch & 1)) * SL_PAIR;
                    uint32_t nWb = nWa + SL_SZ;
                    const __half* srcA = Wa + (size_t)(f0 + 64) * 128;
                    const __half* srcB = Wb + (f0 + 64);
                    for (int i = tid; i < 1024; i += 512) {
                        int r = i >> 4, q = i & 15;
                        cp16h(nWa + r * 272 + q * 16, srcA + (size_t)r * 128 + q * 8);
                    }
                    for (int i = tid; i < 1024; i += 512) {
                        int r = i >> 3, q = i & 7;
                        cp16h(nWb + r * 144 + q * 16, srcB + (size_t)r * 2048 + q * 8);
                    }
                }
                cp_commit();

                // stage 1
                float rf[2][4][4];
#pragma unroll
                for (int m = 0; m < 2; m++)
#pragma unroll
                    for (int n = 0; n < 4; n++)
#pragma unroll
                        for (int e = 0; e < 4; e++) rf[m][n][e] = 0.f;
                {
                    const uint32_t bB = sWa + (wc * 32) * 272 + loff272;
                    uint32_t a[2][4], b[2][4];
#pragma unroll
                    for (int kk = 0; kk < 8; kk++) {
                        ldsm4(a[0], haA + kk * 32);
                        ldsm4(a[1], haA + 16 * 272 + kk * 32);
                        ldsm4(b[0], bB + kk * 32);
                        ldsm4(b[1], bB + 16 * 272 + kk * 32);
#pragma unroll
                        for (int m = 0; m < 2; m++)
#pragma unroll
                            for (int n = 0; n < 4; n++)
                                mma16816(rf[m][n], a[m], b[n >> 1][n & 1], b[n >> 1][(n & 1) + 2]);
                    }
                }
                // mid: bias + relu + pack
#pragma unroll
                for (int m = 0; m < 2; m++)
#pragma unroll
                    for (int n = 0; n < 4; n++) {
                        int c = wc * 32 + n * 8 + (lane & 3) * 2;
                        float2 bias = *(const float2*)&baS[f0 + c];
                        int rowb = r0 + m * 16 + (lane >> 2);
                        __half2 p0 = __floats2half2_rn(fmaxf(rf[m][n][0] + bias.x, 0.f),
                                                       fmaxf(rf[m][n][1] + bias.y, 0.f));
                        *(uint32_t*)(smem + RS_OFF + rowb * 144 + c * 2) = *(uint32_t*)&p0;
                        __half2 p1 = __floats2half2_rn(fmaxf(rf[m][n][2] + bias.x, 0.f),
                                                       fmaxf(rf[m][n][3] + bias.y, 0.f));
                        *(uint32_t*)(smem + RS_OFF + (rowb + 8) * 144 + c * 2) = *(uint32_t*)&p1;
                    }
                asm volatile("bar.sync %0, 64;" :: "r"(1 + wr) : "memory");

                // stage 2
                {
                    const uint32_t aB = sb + RS_OFF + r0 * 144 + loff144;
                    const uint32_t bB = sWb + (wc * 64) * 144 + loff144;
                    uint32_t a[2][4], b[4][4];
#pragma unroll
                    for (int kk = 0; kk < 4; kk++) {
                        ldsm4(a[0], aB + kk * 32);
                        ldsm4(a[1], aB + 16 * 144 + kk * 32);
#pragma unroll
                        for (int g = 0; g < 4; g++) ldsm4(b[g], bB + g * 16 * 144 + kk * 32);
#pragma unroll
                        for (int m = 0; m < 2; m++)
#pragma unroll
                            for (int n = 0; n < 8; n++)
                                mma16816(acc[m][n], a[m], b[n >> 1][n & 1], b[n >> 1][(n & 1) + 2]);
                    }
                }
            }

            // ======== FFN epilogue: LN2 -> hA (l<2) or z-head (l==2) ========
#pragma unroll
            for (int m = 0; m < 2; m++)
#pragma unroll
                for (int h = 0; h < 2; h++) {
                    int lr = r0 + m * 16 + (lane >> 2) + h * 8;
                    int gr = row0 + lr;
                    float ss = 0.f, qq = 0.f;
                    if (gr < N) {
#pragma unroll
                        for (int n = 0; n < 8; n++) {
                            int c = wc * 64 + n * 8 + (lane & 3) * 2;
                            __half2 hh = *(__half2*)(smem + HA_OFF + lr * 272 + c * 2);
                            float2 ho = __half22float2(hh);
                            float v0 = acc[m][n][h * 2 + 0] + ho.x + bb2S[c];
                            float v1 = acc[m][n][h * 2 + 1] + ho.y + bb2S[c + 1];
                            ss += v0 + v1;
                            qq += v0 * v0 + v1 * v1;
                        }
                    }
                    ss += __shfl_xor_sync(0xffffffffu, ss, 1);
                    ss += __shfl_xor_sync(0xffffffffu, ss, 2);
                    qq += __shfl_xor_sync(0xffffffffu, qq, 1);
                    qq += __shfl_xor_sync(0xffffffffu, qq, 2);
                    if ((lane & 3) == 0) red[lr * 2 + wc] = make_float2(ss, qq);
                }
            asm volatile("bar.sync %0, 64;" :: "r"(1 + wr) : "memory");
#pragma unroll
            for (int m = 0; m < 2; m++)
#pragma unroll
                for (int h = 0; h < 2; h++) {
                    int lr = r0 + m * 16 + (lane >> 2) + h * 8;
                    int gr = row0 + lr;
                    float zp = 0.f;
                    if (gr < N) {
                        float2 p0 = red[lr * 2 + 0], p1 = red[lr * 2 + 1];
                        float mean = (p0.x + p1.x) * (1.f / 128.f);
                        float inv = rsqrtf((p0.y + p1.y) * (1.f / 128.f) - mean * mean + 1e-5f);
#pragma unroll
                        for (int n = 0; n < 8; n++) {
                            int c = wc * 64 + n * 8 + (lane & 3) * 2;
                            __half2 hh = *(__half2*)(smem + HA_OFF + lr * 272 + c * 2);
                            float2 ho = __half22float2(hh);
                            float v0 = acc[m][n][h * 2 + 0] + ho.x + bb2S[c];
                            float v1 = acc[m][n][h * 2 + 1] + ho.y + bb2S[c + 1];
                            float o0 = (v0 - mean) * inv * lng2S[c] + lnb2S[c];
                            float o1 = (v1 - mean) * inv * lng2S[c + 1] + lnb2S[c + 1];
                            if (l != 2) {
                                __half2 oo = __floats2half2_rn(o0, o1);
                                *(uint32_t*)(smem + HA_OFF + lr * 272 + c * 2) = *(uint32_t*)&oo;
                            } else {
                                zp += o0 * WdS[c] + o1 * WdS[c + 1];
                            }
                        }
                    }
                    if (l == 2) {
                        zp += __shfl_xor_sync(0xffffffffu, zp, 1);
                        zp += __shfl_xor_sync(0xffffffffu, zp, 2);
                        if ((lane & 3) == 0) zred[lr * 2 + wc] = zp;
                    }
                }
            if (l == 2) {
                asm volatile("bar.sync %0, 64;" :: "r"(1 + wr) : "memory");
#pragma unroll
                for (int m = 0; m < 2; m++)
#pragma unroll
                    for (int h = 0; h < 2; h++) {
                        int lr = r0 + m * 16 + (lane >> 2) + h * 8;
                        int gr = row0 + lr;
                        if (gr < N && (lane & 3) == 0 && wc == 0)
                            g_z[gr] = fmaxf(zred[lr * 2] + zred[lr * 2 + 1] + WdS[128], 0.f);
                    }
            }
            __syncthreads();  // all warps past stage2/epilogue before next layer's G1 writes pair0
        }
    }
}

// ---------------------------------------------------------------------------
__global__ void k_dis_u(int N) {
    int n = blockIdx.x * blockDim.x + threadIdx.x;
    if (n >= N) return;
    float dis = rsqrtf(fmaxf(g_deg[n], 1.0f));
    float u = g_z[n] * dis;
    g_dis[n] = dis;
    g_u[n] = u;
    g_t[n] = u;
}
__global__ void k_scatter(const int* __restrict__ row, const int* __restrict__ col, int E) {
    int e = blockIdx.x * blockDim.x + threadIdx.x;
    if (e < E) atomicAdd(&g_t[col[e]], g_u[row[e]]);
}
__global__ void k_out(const float* __restrict__ Wg, const float* __restrict__ bg,
                      const float* __restrict__ Wf, const float* __restrict__ bf,
                      float* __restrict__ out, int N) {
    int n = blockIdx.x * blockDim.x + threadIdx.x;
    if (n >= N) return;
    float s = g_dis[n] * g_t[n];
    float a = bf[0];
#pragma unroll
    for (int k = 0; k < 32; k++)
        a += fmaxf(s * Wg[k] + bg[k], 0.f) * Wf[k];
    out[n] = a;
}

// ---------------------------------------------------------------------------
extern "C" void kernel_launch(void* const* d_in, const int* in_sizes, int n_in,
                              void* d_out, int out_size) {
    const float* x    = (const float*)d_in[0];
    const int*   edge = (const int*)  d_in[1];
    const float* Win  = (const float*)d_in[2];
    const float* b_in = (const float*)d_in[3];
    const float* Wv   = (const float*)d_in[4];
    const float* bv   = (const float*)d_in[5];
    const float* Wo   = (const float*)d_in[6];
    const float* bo   = (const float*)d_in[7];
    const float* W1   = (const float*)d_in[8];
    const float* b1   = (const float*)d_in[9];
    const float* W2   = (const float*)d_in[10];
    const float* b2   = (const float*)d_in[11];
    const float* ln1g = (const float*)d_in[12];
    const float* ln1b = (const float*)d_in[13];
    const float* ln2g = (const float*)d_in[14];
    const float* ln2b = (const float*)d_in[15];
    const float* Wd   = (const float*)d_in[16];
    const float* bd   = (const float*)d_in[17];
    const float* Wg   = (const float*)d_in[18];
    const float* bg   = (const float*)d_in[19];
    const float* Wf   = (const float*)d_in[20];
    const float* bf   = (const float*)d_in[21];

    const int N = in_sizes[0] / 3;
    const int E = in_sizes[1] / 2;
    const int ntiles = (N + BR - 1) / BR;
    const int degblocks = (N + 255) / 256;

    int sms = 148;
    cudaDeviceGetAttribute(&sms, cudaDevAttrMultiProcessorCount, 0);

    cudaFuncSetAttribute(mega, cudaFuncAttributeMaxDynamicSharedMemorySize, SMEM_BYTES);

    k_prep<<<6576 + degblocks + 1, 256>>>(W1, W2, Wo, Wv, bv, bo, N, degblocks);

    mega<<<sms, 512, SMEM_BYTES>>>(x, Win, b_in, b1, b2, ln1g, ln1b, ln2g, ln2b,
                                   Wd, bd, edge + E, E, N, ntiles);

    k_dis_u<<<(N + 255) / 256, 256>>>(N);
    k_scatter<<<(E + 255) / 256, 256>>>(edge, edge + E, E);
    k_out<<<(N + 255) / 256, 256>>>(Wg, bg, Wf, bf, (float*)d_out, N);
}

// round 12
// speedup vs baseline: 1.0361x; 1.0361x over previous
#include <cuda_runtime.h>
#include <cuda_fp16.h>
#include <cstdint>

#define NMAX 200000
#define D 128
#define BR 256
#define MAXT 800
#define DEGI 296
#define DISI 64
#define SCATI 256
#define OUTI 148

// ---- smem layout (bytes) ----
#define HA_OFF    0        // hA: 256 x 272B
#define RS_OFF    69632    // rS: 256 x 144B
#define SLOTS_OFF 106496   // 2 pairs x (18432 + 18432); Wc uses pair0
#define BA_OFF    180224   // b1 (2048 f); Win(384)+b_in(128) during s0 staging
#define BB_OFF    188416   // attn bias (bc)
#define LNG_OFF   188928
#define LNB_OFF   189440
#define BB2_OFF   189952
#define LNG2_OFF  190464
#define LNB2_OFF  190976
#define RED_OFF   191488   // LN partials float2[256][2]; xS (768 f) during s0 staging
#define ZRED_OFF  195584
#define WD_OFF    197632   // Wd 128 + bd
#define ITEM_OFF  198152
static const int SMEM_BYTES = 198160;
#define SL_PAIR 36864
#define SL_SZ   18432

__device__ __half g_hh[(size_t)NMAX * D];
__device__ float g_z[NMAX];
__device__ float g_deg[NMAX];
__device__ float g_dis[NMAX];
__device__ float g_u[NMAX];
__device__ float g_t[NMAX];
__device__ __half g_wh[1622016];  // [W1 3x262144 | W2 3x262144 | Wc 3x16384]
__device__ float g_bc[384];
__device__ int g_ctr;
__device__ int g_done[3 * MAXT];
__device__ int g_cnt[4];          // 0:s2 tiles, 1:deg, 2:dis, 3:scatter
#define OW1 0
#define OW2 786432
#define OWC 1572864

// ---------------------------------------------------------------------------
static __device__ __forceinline__ uint32_t smem_u32(const void* p) {
    uint32_t r;
    asm("{ .reg .u64 t; cvta.to.shared.u64 t, %1; cvt.u32.u64 %0, t; }" : "=r"(r) : "l"(p));
    return r;
}
static __device__ __forceinline__ void cp16h(uint32_t dst, const __half* src) {
    asm volatile("cp.async.cg.shared.global [%0], [%1], 16;\n" :: "r"(dst), "l"(src));
}
static __device__ __forceinline__ void cp_commit() { asm volatile("cp.async.commit_group;\n"); }
template <int NPEND>
static __device__ __forceinline__ void cp_wait() { asm volatile("cp.async.wait_group %0;\n" :: "n"(NPEND)); }

static __device__ __forceinline__ void ldsm4(uint32_t* r, uint32_t addr) {
    asm volatile("ldmatrix.sync.aligned.m8n8.x4.shared.b16 {%0,%1,%2,%3}, [%4];"
                 : "=r"(r[0]), "=r"(r[1]), "=r"(r[2]), "=r"(r[3]) : "r"(addr));
}
static __device__ __forceinline__ void mma16816(float* c, const uint32_t* a,
                                                uint32_t b0, uint32_t b1) {
    asm volatile("mma.sync.aligned.m16n8k16.row.col.f32.f16.f16.f32 "
                 "{%0,%1,%2,%3}, {%4,%5,%6,%7}, {%8,%9}, {%0,%1,%2,%3};"
                 : "+f"(c[0]), "+f"(c[1]), "+f"(c[2]), "+f"(c[3])
                 : "r"(a[0]), "r"(a[1]), "r"(a[2]), "r"(a[3]), "r"(b0), "r"(b1));
}
static __device__ __forceinline__ float ldcg(const float* p) {
    float v; asm volatile("ld.global.cg.f32 %0, [%1];" : "=f"(v) : "l"(p)); return v;
}
static __device__ __forceinline__ int ldcgi(const int* p) {
    int v; asm volatile("ld.global.cg.s32 %0, [%1];" : "=r"(v) : "l"(p)); return v;
}

// ---------------------------------------------------------------------------
// Merged prep: cvt W1, cvt W2, Wc=Wo@Wv, bc, deg_init, flag/counter reset.
__global__ void k_prep(const float* __restrict__ W1, const float* __restrict__ W2,
                       const float* __restrict__ Wo, const float* __restrict__ Wv,
                       const float* __restrict__ bv, const float* __restrict__ bo,
                       int N, int degblocks) {
    const int b = blockIdx.x, tid = threadIdx.x;
    if (b < 3072) {
        int i = b * 256 + tid;
        g_wh[OW1 + i] = __float2half_rn(W1[i]);
    } else if (b < 6144) {
        int i = (b - 3072) * 256 + tid;
        g_wh[OW2 + i] = __float2half_rn(W2[i]);
    } else if (b < 6528) {
        if (tid < 128) {
            int idx = b - 6144;
            int l = idx >> 7, o = idx & 127, d = tid;
            const float* wo = Wo + (size_t)(l * 128 + o) * 128;
            const float* wv = Wv + (size_t)l * 128 * 128;
            float s = 0.f;
#pragma unroll 8
            for (int k = 0; k < 128; k++) s += wo[k] * wv[k * 128 + d];
            g_wh[OWC + (size_t)(l * 128 + o) * 128 + d] = __float2half_rn(s);
        }
    } else if (b < 6576) {
        int wid = (b - 6528) * 8 + (tid >> 5);
        int lane = tid & 31;
        int l = wid >> 7;
        const float* wo = Wo + (size_t)wid * 128;
        float s = 0.f;
#pragma unroll
        for (int q = 0; q < 4; q++) s += wo[lane + q * 32] * bv[l * 128 + lane + q * 32];
#pragma unroll
        for (int o = 16; o; o >>= 1) s += __shfl_xor_sync(0xffffffffu, s, o);
        if (lane == 0) g_bc[wid] = s + bo[wid];
    } else if (b < 6576 + degblocks) {
        int n = (b - 6576) * 256 + tid;
        if (n < N) g_deg[n] = 1.0f;
    } else {
        if (tid == 0) g_ctr = 0;
        if (tid < 4) g_cnt[tid] = 0;
        for (int i = tid; i < 3 * MAXT; i += 256) g_done[i] = 0;
    }
}

// ---------------------------------------------------------------------------
// Persistent mega: 3 (attn+FFN) stages x ntiles, then deg / dis / scatter / out.
__global__ __launch_bounds__(512, 1)
void mega(const float* __restrict__ x, const float* __restrict__ Win,
          const float* __restrict__ b_in,
          const float* __restrict__ b1, const float* __restrict__ b2,
          const float* __restrict__ ln1g, const float* __restrict__ ln1b,
          const float* __restrict__ ln2g, const float* __restrict__ ln2b,
          const float* __restrict__ Wd, const float* __restrict__ bd,
          const int* __restrict__ rowE, const int* __restrict__ colE,
          const float* __restrict__ Wg, const float* __restrict__ bg,
          const float* __restrict__ Wf, const float* __restrict__ bf,
          float* __restrict__ out, int E, int N, int ntiles) {
    extern __shared__ __align__(256) unsigned char smem[];
    const int tid = threadIdx.x, w = tid >> 5, lane = tid & 31;
    const int wr = w >> 1, wc = w & 1, r0 = wr * 32;
    const uint32_t sb = smem_u32(smem);
    const int NT3 = 3 * ntiles;
    const int IT_DIS = NT3 + DEGI;
    const int IT_SCAT = IT_DIS + DISI;
    const int IT_OUT = IT_SCAT + SCATI;
    const int IT_END = IT_OUT + OUTI;

    float* baS   = (float*)(smem + BA_OFF);
    float* bbS   = (float*)(smem + BB_OFF);
    float* lngS  = (float*)(smem + LNG_OFF);
    float* lnbS  = (float*)(smem + LNB_OFF);
    float* bb2S  = (float*)(smem + BB2_OFF);
    float* lng2S = (float*)(smem + LNG2_OFF);
    float* lnb2S = (float*)(smem + LNB2_OFF);
    float2* red  = (float2*)(smem + RED_OFF);
    float* zred  = (float*)(smem + ZRED_OFF);
    float* WdS   = (float*)(smem + WD_OFF);
    int* shitem  = (int*)(smem + ITEM_OFF);

    const uint32_t loff272 = (lane & 15) * 272 + (lane >> 4) * 16;
    const uint32_t loff144 = (lane & 15) * 144 + (lane >> 4) * 16;
    const uint32_t haA = sb + HA_OFF + r0 * 272 + loff272;

    for (;;) {
        if (tid == 0) *shitem = atomicAdd(&g_ctr, 1);
        __syncthreads();
        const int item = *shitem;
        if (item >= IT_END) return;

        // ================= GCN phases =================
        if (item >= NT3) {
            if (item < IT_DIS) {                     // degree count (independent)
                int di = item - NT3;
                int slice = (E + DEGI - 1) / DEGI;
                int e0 = di * slice, e1 = min(e0 + slice, E);
                for (int e = e0 + tid; e < e1; e += 512)
                    atomicAdd(&g_deg[colE[e]], 1.0f);
                __threadfence();
                __syncthreads();
                if (tid == 0) atomicAdd(&g_cnt[1], 1);
            } else if (item < IT_SCAT) {             // dis/u/t init (needs z + deg)
                if (tid == 0) {
                    while (atomicAdd(&g_cnt[0], 0) < ntiles) __nanosleep(128);
                    while (atomicAdd(&g_cnt[1], 0) < DEGI) __nanosleep(128);
                    __threadfence();
                }
                __syncthreads();
                int di = item - IT_DIS;
                int slice = (N + DISI - 1) / DISI;
                int n0 = di * slice, n1 = min(n0 + slice, N);
                for (int n = n0 + tid; n < n1; n += 512) {
                    float dis = rsqrtf(fmaxf(ldcg(&g_deg[n]), 1.0f));
                    float u = ldcg(&g_z[n]) * dis;
                    g_dis[n] = dis; g_u[n] = u; g_t[n] = u;
                }
                __threadfence();
                __syncthreads();
                if (tid == 0) atomicAdd(&g_cnt[2], 1);
            } else if (item < IT_OUT) {              // edge scatter (needs dis)
                if (tid == 0) {
                    while (atomicAdd(&g_cnt[2], 0) < DISI) __nanosleep(128);
                    __threadfence();
                }
                __syncthreads();
                int di = item - IT_SCAT;
                int slice = (E + SCATI - 1) / SCATI;
                int e0 = di * slice, e1 = min(e0 + slice, E);
                for (int e = e0 + tid; e < e1; e += 512)
                    atomicAdd(&g_t[colE[e]], ldcg(&g_u[rowE[e]]));
                __threadfence();
                __syncthreads();
                if (tid == 0) atomicAdd(&g_cnt[3], 1);
            } else {                                  // output head (needs scatter)
                if (tid == 0) {
                    while (atomicAdd(&g_cnt[3], 0) < SCATI) __nanosleep(128);
                    __threadfence();
                }
                __syncthreads();
                int di = item - IT_OUT;
                int slice = (N + OUTI - 1) / OUTI;
                int n0 = di * slice, n1 = min(n0 + slice, N);
                for (int n = n0 + tid; n < n1; n += 512) {
                    float s = ldcg(&g_dis[n]) * ldcg(&g_t[n]);
                    float a = bf[0];
#pragma unroll
                    for (int k = 0; k < 32; k++)
                        a += fmaxf(s * Wg[k] + bg[k], 0.f) * Wf[k];
                    out[n] = a;
                }
            }
            continue;
        }

        // ================= transformer stage item =================
        const int s = item / ntiles;
        const int t = item - s * ntiles;
        const int row0 = t * BR;

        const __half* Wc = g_wh + OWC + (size_t)s * 16384;
        const __half* Wa = g_wh + OW1 + (size_t)s * 262144;
        const __half* Wb = g_wh + OW2 + (size_t)s * 262144;

        if (s > 0 && tid == 0) {
            while (atomicAdd(&g_done[(s - 1) * ntiles + t], 0) == 0) __nanosleep(64);
            __threadfence();
        }
        __syncthreads();

        // G1 (s>0): hA via cp.async from fp16 g_hh (L2 path, no stale L1)
        if (s > 0) {
            const __half* hsrc = g_hh + (size_t)row0 * D;
            for (int i = tid; i < BR * 16; i += 512) {
                int r = i >> 4, q = i & 15;
                if (row0 + r < N)
                    cp16h(sb + HA_OFF + r * 272 + q * 16, hsrc + (size_t)r * 128 + q * 8);
                else
                    *(uint4*)(smem + HA_OFF + r * 272 + q * 16) = make_uint4(0, 0, 0, 0);
            }
            cp_commit();
        }
        // G: Wc -> pair0
        for (int i = tid; i < 2048; i += 512) {
            int r = i >> 4, q = i & 15;
            cp16h(sb + SLOTS_OFF + r * 272 + q * 16, Wc + (size_t)r * 128 + q * 8);
        }
        cp_commit();
        // G: FFN chunk0 -> pair1
        for (int i = tid; i < 1024; i += 512) {
            int r = i >> 4, q = i & 15;
            cp16h(sb + SLOTS_OFF + SL_PAIR + r * 272 + q * 16, Wa + (size_t)r * 128 + q * 8);
        }
        for (int i = tid; i < 1024; i += 512) {
            int r = i >> 3, q = i & 7;
            cp16h(sb + SLOTS_OFF + SL_PAIR + SL_SZ + r * 144 + q * 16,
                  Wb + (size_t)r * 2048 + q * 8);
        }
        cp_commit();

        // ---- s==0: compute hA = relu(x @ Win^T + b_in) ----
        if (s == 0) {
            float* WinS = baS;
            float* binS = baS + 384;
            float* xS   = (float*)(smem + RED_OFF);
            if (tid < 384) WinS[tid] = Win[tid];
            else if (tid < 512) binS[tid - 384] = b_in[tid - 384];
            for (int i = tid; i < 768; i += 512) {
                int gi = row0 * 3 + i;
                xS[i] = (gi < N * 3) ? x[gi] : 0.f;
            }
            __syncthreads();
            for (int i = tid; i < BR * 64; i += 512) {
                int r = i >> 6, j = i & 63, c = 2 * j;
                int gr = row0 + r;
                float v0 = 0.f, v1 = 0.f;
                if (gr < N) {
                    float x0 = xS[r * 3], x1 = xS[r * 3 + 1], x2 = xS[r * 3 + 2];
                    v0 = fmaxf(binS[c] + x0 * WinS[c * 3] + x1 * WinS[c * 3 + 1]
                               + x2 * WinS[c * 3 + 2], 0.f);
                    v1 = fmaxf(binS[c + 1] + x0 * WinS[(c + 1) * 3] + x1 * WinS[(c + 1) * 3 + 1]
                               + x2 * WinS[(c + 1) * 3 + 2], 0.f);
                }
                __half2 h2 = __floats2half2_rn(v0, v1);
                *(uint32_t*)(smem + HA_OFF + r * 272 + j * 4) = *(uint32_t*)&h2;
            }
        }
        // biases
        if (tid < 128) {
            bbS[tid]   = g_bc[s * 128 + tid];
            lngS[tid]  = ln1g[s * 128 + tid];
            lnbS[tid]  = ln1b[s * 128 + tid];
            bb2S[tid]  = b2[s * 128 + tid];
            lng2S[tid] = ln2g[s * 128 + tid];
            lnb2S[tid] = ln2b[s * 128 + tid];
        }
        if (s == 2) {
            if (tid < 128) WdS[tid] = Wd[tid];
            if (tid == 128) WdS[128] = bd[0];
        }

        cp_wait<1>();     // hA (s>0) + Wc landed; chunk0 may fly
        __syncthreads();

        for (int i = tid; i < 2048; i += 512) baS[i] = b1[s * 2048 + i];

        float acc[2][8][4];
#pragma unroll
        for (int m = 0; m < 2; m++)
#pragma unroll
            for (int n = 0; n < 8; n++)
#pragma unroll
                for (int e = 0; e < 4; e++) acc[m][n][e] = 0.f;

        // ======== attn GEMM: acc = hA @ Wc^T ========
        {
            const uint32_t bB = sb + SLOTS_OFF + (wc * 64) * 272 + loff272;
            uint32_t a[2][4], b[4][4];
#pragma unroll
            for (int kk = 0; kk < 8; kk++) {
                ldsm4(a[0], haA + kk * 32);
                ldsm4(a[1], haA + 16 * 272 + kk * 32);
#pragma unroll
                for (int g = 0; g < 4; g++) ldsm4(b[g], bB + g * 16 * 272 + kk * 32);
#pragma unroll
                for (int m = 0; m < 2; m++)
#pragma unroll
                    for (int n = 0; n < 8; n++)
                        mma16816(acc[m][n], a[m], b[n >> 1][n & 1], b[n >> 1][(n & 1) + 2]);
            }
        }
        __syncthreads();

        // ======== attn epilogue: LN1 -> hA (fp16) ========
#pragma unroll
        for (int m = 0; m < 2; m++)
#pragma unroll
            for (int h = 0; h < 2; h++) {
                int lr = r0 + m * 16 + (lane >> 2) + h * 8;
                int gr = row0 + lr;
                float ss = 0.f, qq = 0.f;
                if (gr < N) {
#pragma unroll
                    for (int n = 0; n < 8; n++) {
                        int c = wc * 64 + n * 8 + (lane & 3) * 2;
                        __half2 hh = *(__half2*)(smem + HA_OFF + lr * 272 + c * 2);
                        float2 ho = __half22float2(hh);
                        float v0 = acc[m][n][h * 2 + 0] + ho.x + bbS[c];
                        float v1 = acc[m][n][h * 2 + 1] + ho.y + bbS[c + 1];
                        ss += v0 + v1;
                        qq += v0 * v0 + v1 * v1;
                    }
                }
                ss += __shfl_xor_sync(0xffffffffu, ss, 1);
                ss += __shfl_xor_sync(0xffffffffu, ss, 2);
                qq += __shfl_xor_sync(0xffffffffu, qq, 1);
                qq += __shfl_xor_sync(0xffffffffu, qq, 2);
                if ((lane & 3) == 0) red[lr * 2 + wc] = make_float2(ss, qq);
            }
        asm volatile("bar.sync %0, 64;" :: "r"(1 + wr) : "memory");
#pragma unroll
        for (int m = 0; m < 2; m++)
#pragma unroll
            for (int h = 0; h < 2; h++) {
                int lr = r0 + m * 16 + (lane >> 2) + h * 8;
                int gr = row0 + lr;
                if (gr >= N) continue;
                float2 p0 = red[lr * 2 + 0], p1 = red[lr * 2 + 1];
                float mean = (p0.x + p1.x) * (1.f / 128.f);
                float inv = rsqrtf((p0.y + p1.y) * (1.f / 128.f) - mean * mean + 1e-5f);
#pragma unroll
                for (int n = 0; n < 8; n++) {
                    int c = wc * 64 + n * 8 + (lane & 3) * 2;
                    __half2 hh = *(__half2*)(smem + HA_OFF + lr * 272 + c * 2);
                    float2 ho = __half22float2(hh);
                    float v0 = acc[m][n][h * 2 + 0] + ho.x + bbS[c];
                    float v1 = acc[m][n][h * 2 + 1] + ho.y + bbS[c + 1];
                    float o0 = (v0 - mean) * inv * lngS[c] + lnbS[c];
                    float o1 = (v1 - mean) * inv * lngS[c + 1] + lnbS[c + 1];
                    __half2 oo = __floats2half2_rn(o0, o1);
                    *(uint32_t*)(smem + HA_OFF + lr * 272 + c * 2) = *(uint32_t*)&oo;
                }
            }
#pragma unroll
        for (int m = 0; m < 2; m++)
#pragma unroll
            for (int n = 0; n < 8; n++)
#pragma unroll
                for (int e = 0; e < 4; e++) acc[m][n][e] = 0.f;

        // ======== FFN: 32 chunks; chunk c in pair ((c+1)&1) ========
        for (int ch = 0; ch < 32; ch++) {
            const int f0 = ch << 6;
            const uint32_t sWa = sb + SLOTS_OFF + (((ch + 1) & 1)) * SL_PAIR;
            const uint32_t sWb = sWa + SL_SZ;

            cp_wait<0>();
            __syncthreads();

            if (ch + 1 < 32) {
                uint32_t nWa = sb + SLOTS_OFF + ((ch & 1)) * SL_PAIR;
                uint32_t nWb = nWa + SL_SZ;
                const __half* srcA = Wa + (size_t)(f0 + 64) * 128;
                const __half* srcB = Wb + (f0 + 64);
                for (int i = tid; i < 1024; i += 512) {
                    int r = i >> 4, q = i & 15;
                    cp16h(nWa + r * 272 + q * 16, srcA + (size_t)r * 128 + q * 8);
                }
                for (int i = tid; i < 1024; i += 512) {
                    int r = i >> 3, q = i & 7;
                    cp16h(nWb + r * 144 + q * 16, srcB + (size_t)r * 2048 + q * 8);
                }
            }
            cp_commit();

            // stage 1
            float rf[2][4][4];
#pragma unroll
            for (int m = 0; m < 2; m++)
#pragma unroll
                for (int n = 0; n < 4; n++)
#pragma unroll
                    for (int e = 0; e < 4; e++) rf[m][n][e] = 0.f;
            {
                const uint32_t bB = sWa + (wc * 32) * 272 + loff272;
                uint32_t a[2][4], b[2][4];
#pragma unroll
                for (int kk = 0; kk < 8; kk++) {
                    ldsm4(a[0], haA + kk * 32);
                    ldsm4(a[1], haA + 16 * 272 + kk * 32);
                    ldsm4(b[0], bB + kk * 32);
                    ldsm4(b[1], bB + 16 * 272 + kk * 32);
#pragma unroll
                    for (int m = 0; m < 2; m++)
#pragma unroll
                        for (int n = 0; n < 4; n++)
                            mma16816(rf[m][n], a[m], b[n >> 1][n & 1], b[n >> 1][(n & 1) + 2]);
                }
            }
            // mid: bias + relu + pack
#pragma unroll
            for (int m = 0; m < 2; m++)
#pragma unroll
                for (int n = 0; n < 4; n++) {
                    int c = wc * 32 + n * 8 + (lane & 3) * 2;
                    float2 bias = *(const float2*)&baS[f0 + c];
                    int rowb = r0 + m * 16 + (lane >> 2);
                    __half2 p0 = __floats2half2_rn(fmaxf(rf[m][n][0] + bias.x, 0.f),
                                                   fmaxf(rf[m][n][1] + bias.y, 0.f));
                    *(uint32_t*)(smem + RS_OFF + rowb * 144 + c * 2) = *(uint32_t*)&p0;
                    __half2 p1 = __floats2half2_rn(fmaxf(rf[m][n][2] + bias.x, 0.f),
                                                   fmaxf(rf[m][n][3] + bias.y, 0.f));
                    *(uint32_t*)(smem + RS_OFF + (rowb + 8) * 144 + c * 2) = *(uint32_t*)&p1;
                }
            asm volatile("bar.sync %0, 64;" :: "r"(1 + wr) : "memory");

            // stage 2
            {
                const uint32_t aB = sb + RS_OFF + r0 * 144 + loff144;
                const uint32_t bB = sWb + (wc * 64) * 144 + loff144;
                uint32_t a[2][4], b[4][4];
#pragma unroll
                for (int kk = 0; kk < 4; kk++) {
                    ldsm4(a[0], aB + kk * 32);
                    ldsm4(a[1], aB + 16 * 144 + kk * 32);
#pragma unroll
                    for (int g = 0; g < 4; g++) ldsm4(b[g], bB + g * 16 * 144 + kk * 32);
#pragma unroll
                    for (int m = 0; m < 2; m++)
#pragma unroll
                        for (int n = 0; n < 8; n++)
                            mma16816(acc[m][n], a[m], b[n >> 1][n & 1], b[n >> 1][(n & 1) + 2]);
                }
            }
        }

        // ======== FFN epilogue: LN2 -> g_hh (s<2) / z-head (s==2) ========
#pragma unroll
        for (int m = 0; m < 2; m++)
#pragma unroll
            for (int h = 0; h < 2; h++) {
                int lr = r0 + m * 16 + (lane >> 2) + h * 8;
                int gr = row0 + lr;
                float ss = 0.f, qq = 0.f;
                if (gr < N) {
#pragma unroll
                    for (int n = 0; n < 8; n++) {
                        int c = wc * 64 + n * 8 + (lane & 3) * 2;
                        __half2 hh = *(__half2*)(smem + HA_OFF + lr * 272 + c * 2);
                        float2 ho = __half22float2(hh);
                        float v0 = acc[m][n][h * 2 + 0] + ho.x + bb2S[c];
                        float v1 = acc[m][n][h * 2 + 1] + ho.y + bb2S[c + 1];
                        ss += v0 + v1;
                        qq += v0 * v0 + v1 * v1;
                    }
                }
                ss += __shfl_xor_sync(0xffffffffu, ss, 1);
                ss += __shfl_xor_sync(0xffffffffu, ss, 2);
                qq += __shfl_xor_sync(0xffffffffu, qq, 1);
                qq += __shfl_xor_sync(0xffffffffu, qq, 2);
                if ((lane & 3) == 0) red[lr * 2 + wc] = make_float2(ss, qq);
            }
        asm volatile("bar.sync %0, 64;" :: "r"(1 + wr) : "memory");
#pragma unroll
        for (int m = 0; m < 2; m++)
#pragma unroll
            for (int h = 0; h < 2; h++) {
                int lr = r0 + m * 16 + (lane >> 2) + h * 8;
                int gr = row0 + lr;
                float zp = 0.f;
                if (gr < N) {
                    float2 p0 = red[lr * 2 + 0], p1 = red[lr * 2 + 1];
                    float mean = (p0.x + p1.x) * (1.f / 128.f);
                    float inv = rsqrtf((p0.y + p1.y) * (1.f / 128.f) - mean * mean + 1e-5f);
#pragma unroll
                    for (int n = 0; n < 8; n++) {
                        int c = wc * 64 + n * 8 + (lane & 3) * 2;
                        __half2 hh = *(__half2*)(smem + HA_OFF + lr * 272 + c * 2);
                        float2 ho = __half22float2(hh);
                        float v0 = acc[m][n][h * 2 + 0] + ho.x + bb2S[c];
                        float v1 = acc[m][n][h * 2 + 1] + ho.y + bb2S[c + 1];
                        float o0 = (v0 - mean) * inv * lng2S[c] + lnb2S[c];
                        float o1 = (v1 - mean) * inv * lng2S[c + 1] + lnb2S[c + 1];
                        if (s != 2) {
                            *(__half2*)(g_hh + (size_t)gr * D + c) = __floats2half2_rn(o0, o1);
                        } else {
                            zp += o0 * WdS[c] + o1 * WdS[c + 1];
                        }
                    }
                }
                if (s == 2) {
                    zp += __shfl_xor_sync(0xffffffffu, zp, 1);
                    zp += __shfl_xor_sync(0xffffffffu, zp, 2);
                    if ((lane & 3) == 0) zred[lr * 2 + wc] = zp;
                }
            }
        if (s == 2) {
            asm volatile("bar.sync %0, 64;" :: "r"(1 + wr) : "memory");
#pragma unroll
            for (int m = 0; m < 2; m++)
#pragma unroll
                for (int h = 0; h < 2; h++) {
                    int lr = r0 + m * 16 + (lane >> 2) + h * 8;
                    int gr = row0 + lr;
                    if (gr < N && (lane & 3) == 0 && wc == 0)
                        g_z[gr] = fmaxf(zred[lr * 2] + zred[lr * 2 + 1] + WdS[128], 0.f);
                }
        }

        __threadfence();
        __syncthreads();
        if (tid == 0) {
            if (s < 2) atomicExch(&g_done[s * ntiles + t], 1);
            else atomicAdd(&g_cnt[0], 1);
        }
    }
}

// ---------------------------------------------------------------------------
extern "C" void kernel_launch(void* const* d_in, const int* in_sizes, int n_in,
                              void* d_out, int out_size) {
    const float* x    = (const float*)d_in[0];
    const int*   edge = (const int*)  d_in[1];
    const float* Win  = (const float*)d_in[2];
    const float* b_in = (const float*)d_in[3];
    const float* Wv   = (const float*)d_in[4];
    const float* bv   = (const float*)d_in[5];
    const float* Wo   = (const float*)d_in[6];
    const float* bo   = (const float*)d_in[7];
    const float* W1   = (const float*)d_in[8];
    const float* b1   = (const float*)d_in[9];
    const float* W2   = (const float*)d_in[10];
    const float* b2   = (const float*)d_in[11];
    const float* ln1g = (const float*)d_in[12];
    const float* ln1b = (const float*)d_in[13];
    const float* ln2g = (const float*)d_in[14];
    const float* ln2b = (const float*)d_in[15];
    const float* Wd   = (const float*)d_in[16];
    const float* bd   = (const float*)d_in[17];
    const float* Wg   = (const float*)d_in[18];
    const float* bg   = (const float*)d_in[19];
    const float* Wf   = (const float*)d_in[20];
    const float* bf   = (const float*)d_in[21];

    const int N = in_sizes[0] / 3;
    const int E = in_sizes[1] / 2;
    const int ntiles = (N + BR - 1) / BR;
    const int degblocks = (N + 255) / 256;

    int sms = 148;
    cudaDeviceGetAttribute(&sms, cudaDevAttrMultiProcessorCount, 0);

    cudaFuncSetAttribute(mega, cudaFuncAttributeMaxDynamicSharedMemorySize, SMEM_BYTES);

    k_prep<<<6576 + degblocks + 1, 256>>>(W1, W2, Wo, Wv, bv, bo, N, degblocks);

    mega<<<sms, 512, SMEM_BYTES>>>(x, Win, b_in, b1, b2, ln1g, ln1b, ln2g, ln2b,
                                   Wd, bd, edge, edge + E, Wg, bg, Wf, bf,
                                   (float*)d_out, E, N, ntiles);
}

// round 13
// speedup vs baseline: 1.0448x; 1.0084x over previous
#include <cuda_runtime.h>
#include <cuda_fp16.h>
#include <cstdint>

#define NMAX 200000
#define D 128
#define BR 256
#define MAXT 800
#define DEGI 296

// ---- smem layout (bytes) ----
#define HA_OFF    0        // hA: 256 x 272B
#define RS_OFF    69632    // rS: 256 x 144B
#define SLOTS_OFF 106496   // 2 pairs x (18432 + 18432); Wc uses pair0
#define BA_OFF    180224   // b1 (2048 f); Win(384)+b_in(128) during s0 staging
#define BB_OFF    188416   // attn bias (bc)
#define LNG_OFF   188928
#define LNB_OFF   189440
#define BB2_OFF   189952
#define LNG2_OFF  190464
#define LNB2_OFF  190976
#define RED_OFF   191488   // LN partials float2[256][2]; xS (768 f) during s0 staging
#define ZRED_OFF  195584
#define WD_OFF    197632   // Wd 128 + bd
#define ITEM_OFF  198152
static const int SMEM_BYTES = 198160;
#define SL_PAIR 36864
#define SL_SZ   18432

__device__ __half g_hh[(size_t)NMAX * D];
__device__ float g_z[NMAX];
__device__ float g_deg[NMAX];
__device__ float g_dis[NMAX];
__device__ float g_u[NMAX];
__device__ float g_t[NMAX];
__device__ __half g_wh[1622016];  // [W1 3x262144 | W2 3x262144 | Wc 3x16384]
__device__ float g_bc[384];
__device__ int g_ctr;
__device__ int g_done[3 * MAXT];
#define OW1 0
#define OW2 786432
#define OWC 1572864

// ---------------------------------------------------------------------------
static __device__ __forceinline__ uint32_t smem_u32(const void* p) {
    uint32_t r;
    asm("{ .reg .u64 t; cvta.to.shared.u64 t, %1; cvt.u32.u64 %0, t; }" : "=r"(r) : "l"(p));
    return r;
}
static __device__ __forceinline__ void cp16h(uint32_t dst, const __half* src) {
    asm volatile("cp.async.cg.shared.global [%0], [%1], 16;\n" :: "r"(dst), "l"(src));
}
static __device__ __forceinline__ void cp_commit() { asm volatile("cp.async.commit_group;\n"); }
template <int NPEND>
static __device__ __forceinline__ void cp_wait() { asm volatile("cp.async.wait_group %0;\n" :: "n"(NPEND)); }

static __device__ __forceinline__ void ldsm4(uint32_t* r, uint32_t addr) {
    asm volatile("ldmatrix.sync.aligned.m8n8.x4.shared.b16 {%0,%1,%2,%3}, [%4];"
                 : "=r"(r[0]), "=r"(r[1]), "=r"(r[2]), "=r"(r[3]) : "r"(addr));
}
static __device__ __forceinline__ void mma16816(float* c, const uint32_t* a,
                                                uint32_t b0, uint32_t b1) {
    asm volatile("mma.sync.aligned.m16n8k16.row.col.f32.f16.f16.f32 "
                 "{%0,%1,%2,%3}, {%4,%5,%6,%7}, {%8,%9}, {%0,%1,%2,%3};"
                 : "+f"(c[0]), "+f"(c[1]), "+f"(c[2]), "+f"(c[3])
                 : "r"(a[0]), "r"(a[1]), "r"(a[2]), "r"(a[3]), "r"(b0), "r"(b1));
}

// ---------------------------------------------------------------------------
// Merged prep: cvt W1, cvt W2, Wc=Wo@Wv, bc, deg_init, flag/counter reset.
__global__ void k_prep(const float* __restrict__ W1, const float* __restrict__ W2,
                       const float* __restrict__ Wo, const float* __restrict__ Wv,
                       const float* __restrict__ bv, const float* __restrict__ bo,
                       int N, int degblocks) {
    const int b = blockIdx.x, tid = threadIdx.x;
    if (b < 3072) {
        int i = b * 256 + tid;
        g_wh[OW1 + i] = __float2half_rn(W1[i]);
    } else if (b < 6144) {
        int i = (b - 3072) * 256 + tid;
        g_wh[OW2 + i] = __float2half_rn(W2[i]);
    } else if (b < 6528) {
        if (tid < 128) {
            int idx = b - 6144;
            int l = idx >> 7, o = idx & 127, d = tid;
            const float* wo = Wo + (size_t)(l * 128 + o) * 128;
            const float* wv = Wv + (size_t)l * 128 * 128;
            float s = 0.f;
#pragma unroll 8
            for (int k = 0; k < 128; k++) s += wo[k] * wv[k * 128 + d];
            g_wh[OWC + (size_t)(l * 128 + o) * 128 + d] = __float2half_rn(s);
        }
    } else if (b < 6576) {
        int wid = (b - 6528) * 8 + (tid >> 5);
        int lane = tid & 31;
        int l = wid >> 7;
        const float* wo = Wo + (size_t)wid * 128;
        float s = 0.f;
#pragma unroll
        for (int q = 0; q < 4; q++) s += wo[lane + q * 32] * bv[l * 128 + lane + q * 32];
#pragma unroll
        for (int o = 16; o; o >>= 1) s += __shfl_xor_sync(0xffffffffu, s, o);
        if (lane == 0) g_bc[wid] = s + bo[wid];
    } else if (b < 6576 + degblocks) {
        int n = (b - 6576) * 256 + tid;
        if (n < N) g_deg[n] = 1.0f;
    } else {
        if (tid == 0) g_ctr = 0;
        for (int i = tid; i < 3 * MAXT; i += 256) g_done[i] = 0;
    }
}

// ---------------------------------------------------------------------------
// Persistent mega: 3 (attn+FFN) stages x ntiles + independent deg items.
__global__ __launch_bounds__(512, 1)
void mega(const float* __restrict__ x, const float* __restrict__ Win,
          const float* __restrict__ b_in,
          const float* __restrict__ b1, const float* __restrict__ b2,
          const float* __restrict__ ln1g, const float* __restrict__ ln1b,
          const float* __restrict__ ln2g, const float* __restrict__ ln2b,
          const float* __restrict__ Wd, const float* __restrict__ bd,
          const int* __restrict__ colE, int E, int N, int ntiles) {
    extern __shared__ __align__(256) unsigned char smem[];
    const int tid = threadIdx.x, w = tid >> 5, lane = tid & 31;
    const int wr = w >> 1, wc = w & 1, r0 = wr * 32;
    const uint32_t sb = smem_u32(smem);
    const int NT3 = 3 * ntiles;

    float* baS   = (float*)(smem + BA_OFF);
    float* bbS   = (float*)(smem + BB_OFF);
    float* lngS  = (float*)(smem + LNG_OFF);
    float* lnbS  = (float*)(smem + LNB_OFF);
    float* bb2S  = (float*)(smem + BB2_OFF);
    float* lng2S = (float*)(smem + LNG2_OFF);
    float* lnb2S = (float*)(smem + LNB2_OFF);
    float2* red  = (float2*)(smem + RED_OFF);
    float* zred  = (float*)(smem + ZRED_OFF);
    float* WdS   = (float*)(smem + WD_OFF);
    int* shitem  = (int*)(smem + ITEM_OFF);

    const uint32_t loff272 = (lane & 15) * 272 + (lane >> 4) * 16;
    const uint32_t loff144 = (lane & 15) * 144 + (lane >> 4) * 16;
    const uint32_t haA = sb + HA_OFF + r0 * 272 + loff272;

    for (;;) {
        if (tid == 0) *shitem = atomicAdd(&g_ctr, 1);
        __syncthreads();
        const int item = *shitem;
        if (item >= NT3 + DEGI) return;
        if (item >= NT3) {                           // degree count (independent)
            int di = item - NT3;
            int slice = (E + DEGI - 1) / DEGI;
            int e0 = di * slice, e1 = min(e0 + slice, E);
            for (int e = e0 + tid; e < e1; e += 512)
                atomicAdd(&g_deg[colE[e]], 1.0f);
            continue;
        }

        // ================= transformer stage item =================
        const int s = item / ntiles;
        const int t = item - s * ntiles;
        const int row0 = t * BR;

        const __half* Wc = g_wh + OWC + (size_t)s * 16384;
        const __half* Wa = g_wh + OW1 + (size_t)s * 262144;
        const __half* Wb = g_wh + OW2 + (size_t)s * 262144;

        if (s > 0 && tid == 0) {
            while (atomicAdd(&g_done[(s - 1) * ntiles + t], 0) == 0) __nanosleep(64);
            __threadfence();
        }
        __syncthreads();

        // G1 (s>0): hA via cp.async from fp16 g_hh (L2 path, no stale L1)
        if (s > 0) {
            const __half* hsrc = g_hh + (size_t)row0 * D;
            for (int i = tid; i < BR * 16; i += 512) {
                int r = i >> 4, q = i & 15;
                if (row0 + r < N)
                    cp16h(sb + HA_OFF + r * 272 + q * 16, hsrc + (size_t)r * 128 + q * 8);
                else
                    *(uint4*)(smem + HA_OFF + r * 272 + q * 16) = make_uint4(0, 0, 0, 0);
            }
            cp_commit();
        }
        // G: Wc -> pair0
        for (int i = tid; i < 2048; i += 512) {
            int r = i >> 4, q = i & 15;
            cp16h(sb + SLOTS_OFF + r * 272 + q * 16, Wc + (size_t)r * 128 + q * 8);
        }
        cp_commit();
        // G: FFN chunk0 -> pair1
        for (int i = tid; i < 1024; i += 512) {
            int r = i >> 4, q = i & 15;
            cp16h(sb + SLOTS_OFF + SL_PAIR + r * 272 + q * 16, Wa + (size_t)r * 128 + q * 8);
        }
        for (int i = tid; i < 1024; i += 512) {
            int r = i >> 3, q = i & 7;
            cp16h(sb + SLOTS_OFF + SL_PAIR + SL_SZ + r * 144 + q * 16,
                  Wb + (size_t)r * 2048 + q * 8);
        }
        cp_commit();

        // ---- s==0: compute hA = relu(x @ Win^T + b_in) ----
        if (s == 0) {
            float* WinS = baS;
            float* binS = baS + 384;
            float* xS   = (float*)(smem + RED_OFF);
            if (tid < 384) WinS[tid] = Win[tid];
            else if (tid < 512) binS[tid - 384] = b_in[tid - 384];
            for (int i = tid; i < 768; i += 512) {
                int gi = row0 * 3 + i;
                xS[i] = (gi < N * 3) ? x[gi] : 0.f;
            }
            __syncthreads();
            for (int i = tid; i < BR * 64; i += 512) {
                int r = i >> 6, j = i & 63, c = 2 * j;
                int gr = row0 + r;
                float v0 = 0.f, v1 = 0.f;
                if (gr < N) {
                    float x0 = xS[r * 3], x1 = xS[r * 3 + 1], x2 = xS[r * 3 + 2];
                    v0 = fmaxf(binS[c] + x0 * WinS[c * 3] + x1 * WinS[c * 3 + 1]
                               + x2 * WinS[c * 3 + 2], 0.f);
                    v1 = fmaxf(binS[c + 1] + x0 * WinS[(c + 1) * 3] + x1 * WinS[(c + 1) * 3 + 1]
                               + x2 * WinS[(c + 1) * 3 + 2], 0.f);
                }
                __half2 h2 = __floats2half2_rn(v0, v1);
                *(uint32_t*)(smem + HA_OFF + r * 272 + j * 4) = *(uint32_t*)&h2;
            }
        }
        // biases
        if (tid < 128) {
            bbS[tid]   = g_bc[s * 128 + tid];
            lngS[tid]  = ln1g[s * 128 + tid];
            lnbS[tid]  = ln1b[s * 128 + tid];
            bb2S[tid]  = b2[s * 128 + tid];
            lng2S[tid] = ln2g[s * 128 + tid];
            lnb2S[tid] = ln2b[s * 128 + tid];
        }
        if (s == 2) {
            if (tid < 128) WdS[tid] = Wd[tid];
            if (tid == 128) WdS[128] = bd[0];
        }

        cp_wait<1>();     // hA (s>0) + Wc landed; chunk0 may fly
        __syncthreads();

        for (int i = tid; i < 2048; i += 512) baS[i] = b1[s * 2048 + i];

        float acc[2][8][4];
#pragma unroll
        for (int m = 0; m < 2; m++)
#pragma unroll
            for (int n = 0; n < 8; n++)
#pragma unroll
                for (int e = 0; e < 4; e++) acc[m][n][e] = 0.f;

        // ======== attn GEMM: acc = hA @ Wc^T ========
        {
            const uint32_t bB = sb + SLOTS_OFF + (wc * 64) * 272 + loff272;
            uint32_t a[2][4], b[4][4];
#pragma unroll
            for (int kk = 0; kk < 8; kk++) {
                ldsm4(a[0], haA + kk * 32);
                ldsm4(a[1], haA + 16 * 272 + kk * 32);
#pragma unroll
                for (int g = 0; g < 4; g++) ldsm4(b[g], bB + g * 16 * 272 + kk * 32);
#pragma unroll
                for (int m = 0; m < 2; m++)
#pragma unroll
                    for (int n = 0; n < 8; n++)
                        mma16816(acc[m][n], a[m], b[n >> 1][n & 1], b[n >> 1][(n & 1) + 2]);
            }
        }
        __syncthreads();

        // ======== attn epilogue: LN1 -> hA (fp16) ========
#pragma unroll
        for (int m = 0; m < 2; m++)
#pragma unroll
            for (int h = 0; h < 2; h++) {
                int lr = r0 + m * 16 + (lane >> 2) + h * 8;
                int gr = row0 + lr;
                float ss = 0.f, qq = 0.f;
                if (gr < N) {
#pragma unroll
                    for (int n = 0; n < 8; n++) {
                        int c = wc * 64 + n * 8 + (lane & 3) * 2;
                        __half2 hh = *(__half2*)(smem + HA_OFF + lr * 272 + c * 2);
                        float2 ho = __half22float2(hh);
                        float v0 = acc[m][n][h * 2 + 0] + ho.x + bbS[c];
                        float v1 = acc[m][n][h * 2 + 1] + ho.y + bbS[c + 1];
                        ss += v0 + v1;
                        qq += v0 * v0 + v1 * v1;
                    }
                }
                ss += __shfl_xor_sync(0xffffffffu, ss, 1);
                ss += __shfl_xor_sync(0xffffffffu, ss, 2);
                qq += __shfl_xor_sync(0xffffffffu, qq, 1);
                qq += __shfl_xor_sync(0xffffffffu, qq, 2);
                if ((lane & 3) == 0) red[lr * 2 + wc] = make_float2(ss, qq);
            }
        asm volatile("bar.sync %0, 64;" :: "r"(1 + wr) : "memory");
#pragma unroll
        for (int m = 0; m < 2; m++)
#pragma unroll
            for (int h = 0; h < 2; h++) {
                int lr = r0 + m * 16 + (lane >> 2) + h * 8;
                int gr = row0 + lr;
                if (gr >= N) continue;
                float2 p0 = red[lr * 2 + 0], p1 = red[lr * 2 + 1];
                float mean = (p0.x + p1.x) * (1.f / 128.f);
                float inv = rsqrtf((p0.y + p1.y) * (1.f / 128.f) - mean * mean + 1e-5f);
#pragma unroll
                for (int n = 0; n < 8; n++) {
                    int c = wc * 64 + n * 8 + (lane & 3) * 2;
                    __half2 hh = *(__half2*)(smem + HA_OFF + lr * 272 + c * 2);
                    float2 ho = __half22float2(hh);
                    float v0 = acc[m][n][h * 2 + 0] + ho.x + bbS[c];
                    float v1 = acc[m][n][h * 2 + 1] + ho.y + bbS[c + 1];
                    float o0 = (v0 - mean) * inv * lngS[c] + lnbS[c];
                    float o1 = (v1 - mean) * inv * lngS[c + 1] + lnbS[c + 1];
                    __half2 oo = __floats2half2_rn(o0, o1);
                    *(uint32_t*)(smem + HA_OFF + lr * 272 + c * 2) = *(uint32_t*)&oo;
                }
            }
#pragma unroll
        for (int m = 0; m < 2; m++)
#pragma unroll
            for (int n = 0; n < 8; n++)
#pragma unroll
                for (int e = 0; e < 4; e++) acc[m][n][e] = 0.f;

        // ======== FFN: 32 chunks; chunk c in pair ((c+1)&1) ========
        for (int ch = 0; ch < 32; ch++) {
            const int f0 = ch << 6;
            const uint32_t sWa = sb + SLOTS_OFF + (((ch + 1) & 1)) * SL_PAIR;
            const uint32_t sWb = sWa + SL_SZ;

            cp_wait<0>();
            __syncthreads();

            if (ch + 1 < 32) {
                uint32_t nWa = sb + SLOTS_OFF + ((ch & 1)) * SL_PAIR;
                uint32_t nWb = nWa + SL_SZ;
                const __half* srcA = Wa + (size_t)(f0 + 64) * 128;
                const __half* srcB = Wb + (f0 + 64);
                for (int i = tid; i < 1024; i += 512) {
                    int r = i >> 4, q = i & 15;
                    cp16h(nWa + r * 272 + q * 16, srcA + (size_t)r * 128 + q * 8);
                }
                for (int i = tid; i < 1024; i += 512) {
                    int r = i >> 3, q = i & 7;
                    cp16h(nWb + r * 144 + q * 16, srcB + (size_t)r * 2048 + q * 8);
                }
            }
            cp_commit();

            // stage 1
            float rf[2][4][4];
#pragma unroll
            for (int m = 0; m < 2; m++)
#pragma unroll
                for (int n = 0; n < 4; n++)
#pragma unroll
                    for (int e = 0; e < 4; e++) rf[m][n][e] = 0.f;
            {
                const uint32_t bB = sWa + (wc * 32) * 272 + loff272;
                uint32_t a[2][4], b[2][4];
#pragma unroll
                for (int kk = 0; kk < 8; kk++) {
                    ldsm4(a[0], haA + kk * 32);
                    ldsm4(a[1], haA + 16 * 272 + kk * 32);
                    ldsm4(b[0], bB + kk * 32);
                    ldsm4(b[1], bB + 16 * 272 + kk * 32);
#pragma unroll
                    for (int m = 0; m < 2; m++)
#pragma unroll
                        for (int n = 0; n < 4; n++)
                            mma16816(rf[m][n], a[m], b[n >> 1][n & 1], b[n >> 1][(n & 1) + 2]);
                }
            }
            // mid: bias + relu + pack; KEEP packed values (they are stage-2 A
            // operand fragments for this warp's own k-half) and store to rS for
            // the partner warp.
            uint32_t pk[2][4][2];
#pragma unroll
            for (int m = 0; m < 2; m++)
#pragma unroll
                for (int n = 0; n < 4; n++) {
                    int c = wc * 32 + n * 8 + (lane & 3) * 2;
                    float2 bias = *(const float2*)&baS[f0 + c];
                    int rowb = r0 + m * 16 + (lane >> 2);
                    __half2 p0 = __floats2half2_rn(fmaxf(rf[m][n][0] + bias.x, 0.f),
                                                   fmaxf(rf[m][n][1] + bias.y, 0.f));
                    pk[m][n][0] = *(uint32_t*)&p0;
                    *(uint32_t*)(smem + RS_OFF + rowb * 144 + c * 2) = pk[m][n][0];
                    __half2 p1 = __floats2half2_rn(fmaxf(rf[m][n][2] + bias.x, 0.f),
                                                   fmaxf(rf[m][n][3] + bias.y, 0.f));
                    pk[m][n][1] = *(uint32_t*)&p1;
                    *(uint32_t*)(smem + RS_OFF + (rowb + 8) * 144 + c * 2) = pk[m][n][1];
                }
            asm volatile("bar.sync %0, 64;" :: "r"(1 + wr) : "memory");

            // stage 2: own k-half A from registers, partner half from rS
            {
                const uint32_t aB = sb + RS_OFF + r0 * 144 + loff144;
                const uint32_t bB = sWb + (wc * 64) * 144 + loff144;
                uint32_t a[2][4], b[4][4];
#pragma unroll
                for (int kk = 0; kk < 4; kk++) {
                    if ((kk >> 1) == wc) {
                        int j = kk & 1;
#pragma unroll
                        for (int m = 0; m < 2; m++) {
                            a[m][0] = pk[m][2 * j][0];
                            a[m][1] = pk[m][2 * j][1];
                            a[m][2] = pk[m][2 * j + 1][0];
                            a[m][3] = pk[m][2 * j + 1][1];
                        }
                    } else {
                        ldsm4(a[0], aB + kk * 32);
                        ldsm4(a[1], aB + 16 * 144 + kk * 32);
                    }
#pragma unroll
                    for (int g = 0; g < 4; g++) ldsm4(b[g], bB + g * 16 * 144 + kk * 32);
#pragma unroll
                    for (int m = 0; m < 2; m++)
#pragma unroll
                        for (int n = 0; n < 8; n++)
                            mma16816(acc[m][n], a[m], b[n >> 1][n & 1], b[n >> 1][(n & 1) + 2]);
                }
            }
        }

        // ======== FFN epilogue: LN2 -> g_hh (s<2) / z-head (s==2) ========
#pragma unroll
        for (int m = 0; m < 2; m++)
#pragma unroll
            for (int h = 0; h < 2; h++) {
                int lr = r0 + m * 16 + (lane >> 2) + h * 8;
                int gr = row0 + lr;
                float ss = 0.f, qq = 0.f;
                if (gr < N) {
#pragma unroll
                    for (int n = 0; n < 8; n++) {
                        int c = wc * 64 + n * 8 + (lane & 3) * 2;
                        __half2 hh = *(__half2*)(smem + HA_OFF + lr * 272 + c * 2);
                        float2 ho = __half22float2(hh);
                        float v0 = acc[m][n][h * 2 + 0] + ho.x + bb2S[c];
                        float v1 = acc[m][n][h * 2 + 1] + ho.y + bb2S[c + 1];
                        ss += v0 + v1;
                        qq += v0 * v0 + v1 * v1;
                    }
                }
                ss += __shfl_xor_sync(0xffffffffu, ss, 1);
                ss += __shfl_xor_sync(0xffffffffu, ss, 2);
                qq += __shfl_xor_sync(0xffffffffu, qq, 1);
                qq += __shfl_xor_sync(0xffffffffu, qq, 2);
                if ((lane & 3) == 0) red[lr * 2 + wc] = make_float2(ss, qq);
            }
        asm volatile("bar.sync %0, 64;" :: "r"(1 + wr) : "memory");
#pragma unroll
        for (int m = 0; m < 2; m++)
#pragma unroll
            for (int h = 0; h < 2; h++) {
                int lr = r0 + m * 16 + (lane >> 2) + h * 8;
                int gr = row0 + lr;
                float zp = 0.f;
                if (gr < N) {
                    float2 p0 = red[lr * 2 + 0], p1 = red[lr * 2 + 1];
                    float mean = (p0.x + p1.x) * (1.f / 128.f);
                    float inv = rsqrtf((p0.y + p1.y) * (1.f / 128.f) - mean * mean + 1e-5f);
#pragma unroll
                    for (int n = 0; n < 8; n++) {
                        int c = wc * 64 + n * 8 + (lane & 3) * 2;
                        __half2 hh = *(__half2*)(smem + HA_OFF + lr * 272 + c * 2);
                        float2 ho = __half22float2(hh);
                        float v0 = acc[m][n][h * 2 + 0] + ho.x + bb2S[c];
                        float v1 = acc[m][n][h * 2 + 1] + ho.y + bb2S[c + 1];
                        float o0 = (v0 - mean) * inv * lng2S[c] + lnb2S[c];
                        float o1 = (v1 - mean) * inv * lng2S[c + 1] + lnb2S[c + 1];
                        if (s != 2) {
                            *(__half2*)(g_hh + (size_t)gr * D + c) = __floats2half2_rn(o0, o1);
                        } else {
                            zp += o0 * WdS[c] + o1 * WdS[c + 1];
                        }
                    }
                }
                if (s == 2) {
                    zp += __shfl_xor_sync(0xffffffffu, zp, 1);
                    zp += __shfl_xor_sync(0xffffffffu, zp, 2);
                    if ((lane & 3) == 0) zred[lr * 2 + wc] = zp;
                }
            }
        if (s == 2) {
            asm volatile("bar.sync %0, 64;" :: "r"(1 + wr) : "memory");
#pragma unroll
            for (int m = 0; m < 2; m++)
#pragma unroll
                for (int h = 0; h < 2; h++) {
                    int lr = r0 + m * 16 + (lane >> 2) + h * 8;
                    int gr = row0 + lr;
                    if (gr < N && (lane & 3) == 0 && wc == 0)
                        g_z[gr] = fmaxf(zred[lr * 2] + zred[lr * 2 + 1] + WdS[128], 0.f);
                }
        }

        __threadfence();
        __syncthreads();
        if (tid == 0 && s < 2) atomicExch(&g_done[s * ntiles + t], 1);
    }
}

// ---------------------------------------------------------------------------
__global__ void k_dis_u(int N) {
    int n = blockIdx.x * blockDim.x + threadIdx.x;
    if (n >= N) return;
    float dis = rsqrtf(fmaxf(g_deg[n], 1.0f));
    float u = g_z[n] * dis;
    g_dis[n] = dis;
    g_u[n] = u;
    g_t[n] = u;
}
__global__ void k_scatter(const int* __restrict__ row, const int* __restrict__ col, int E) {
    int e = blockIdx.x * blockDim.x + threadIdx.x;
    if (e < E) atomicAdd(&g_t[col[e]], g_u[row[e]]);
}
__global__ void k_out(const float* __restrict__ Wg, const float* __restrict__ bg,
                      const float* __restrict__ Wf, const float* __restrict__ bf,
                      float* __restrict__ out, int N) {
    int n = blockIdx.x * blockDim.x + threadIdx.x;
    if (n >= N) return;
    float s = g_dis[n] * g_t[n];
    float a = bf[0];
#pragma unroll
    for (int k = 0; k < 32; k++)
        a += fmaxf(s * Wg[k] + bg[k], 0.f) * Wf[k];
    out[n] = a;
}

// ---------------------------------------------------------------------------
extern "C" void kernel_launch(void* const* d_in, const int* in_sizes, int n_in,
                              void* d_out, int out_size) {
    const float* x    = (const float*)d_in[0];
    const int*   edge = (const int*)  d_in[1];
    const float* Win  = (const float*)d_in[2];
    const float* b_in = (const float*)d_in[3];
    const float* Wv   = (const float*)d_in[4];
    const float* bv   = (const float*)d_in[5];
    const float* Wo   = (const float*)d_in[6];
    const float* bo   = (const float*)d_in[7];
    const float* W1   = (const float*)d_in[8];
    const float* b1   = (const float*)d_in[9];
    const float* W2   = (const float*)d_in[10];
    const float* b2   = (const float*)d_in[11];
    const float* ln1g = (const float*)d_in[12];
    const float* ln1b = (const float*)d_in[13];
    const float* ln2g = (const float*)d_in[14];
    const float* ln2b = (const float*)d_in[15];
    const float* Wd   = (const float*)d_in[16];
    const float* bd   = (const float*)d_in[17];
    const float* Wg   = (const float*)d_in[18];
    const float* bg   = (const float*)d_in[19];
    const float* Wf   = (const float*)d_in[20];
    const float* bf   = (const float*)d_in[21];

    const int N = in_sizes[0] / 3;
    const int E = in_sizes[1] / 2;
    const int ntiles = (N + BR - 1) / BR;
    const int degblocks = (N + 255) / 256;

    int sms = 148;
    cudaDeviceGetAttribute(&sms, cudaDevAttrMultiProcessorCount, 0);

    cudaFuncSetAttribute(mega, cudaFuncAttributeMaxDynamicSharedMemorySize, SMEM_BYTES);

    k_prep<<<6576 + degblocks + 1, 256>>>(W1, W2, Wo, Wv, bv, bo, N, degblocks);

    mega<<<sms, 512, SMEM_BYTES>>>(x, Win, b_in, b1, b2, ln1g, ln1b, ln2g, ln2b,
                                   Wd, bd, edge + E, E, N, ntiles);

    k_dis_u<<<(N + 255) / 256, 256>>>(N);
    k_scatter<<<(E + 255) / 256, 256>>>(edge, edge + E, E);
    k_out<<<(N + 255) / 256, 256>>>(Wg, bg, Wf, bf, (float*)d_out, N);
}